// round 14
// baseline (speedup 1.0000x reference)
#include <cuda_runtime.h>
#include <cuda_bf16.h>
#include <mma.h>
#include <cfloat>
#include <cstdint>

using namespace nvcuda;

#define L_  8
#define D_  1024
#define H_  16
#define T_  1024
#define V_  2048
#define B_  8
#define DH_ 64
#define FF_ 4096
#define M_  (B_ * T_)   // 8192 rows
#define MD_ ((size_t)M_ * D_)   // 8,388,608
#define WD_SZ ((size_t)D_ * D_)
#define LW_SZ (4 * WD_SZ + (size_t)D_ * FF_ + (size_t)FF_ * D_)

// ---------------- scratch (device globals; no allocation allowed) -------------
__device__ float g_x [ MD_ ];                       // fp32 residual stream

// pre-split activations (hi/lo bf16): h | q | k | v | o | ff
#define ACT_TOT ((size_t)M_ * (5 * D_ + FF_))       // 75,497,472
__device__ __nv_bfloat16 g_ah[ACT_TOT];
__device__ __nv_bfloat16 g_al[ACT_TOT];

// Transposed + bf16-split weights: [N,K] K-major, hi and lo parts.
#define WTOT 102760448ULL
__device__ __nv_bfloat16 g_whi[WTOT];
__device__ __nv_bfloat16 g_wlo[WTOT];

// combined qkv bias per layer [L][3072]
__device__ float g_bqkv[L_ * 3 * D_];

// ---------------- helpers ----------------------------------------------------
__device__ __forceinline__ float gelu_f(float x) {
    return 0.5f * x * (1.0f + erff(x * 0.70710678118654752f));
}

// pack two floats into bf16x2 hi + residual lo
__device__ __forceinline__ void pack_split2(float x, float y, uint32_t& h, uint32_t& l) {
    asm("cvt.rn.bf16x2.f32 %0, %1, %2;" : "=r"(h) : "f"(y), "f"(x));
    float hx = __uint_as_float(h << 16);
    float hy = __uint_as_float(h & 0xffff0000u);
    asm("cvt.rn.bf16x2.f32 %0, %1, %2;" : "=r"(l) : "f"(y - hy), "f"(x - hx));
}

// raw bf16 mma m16n8k16
__device__ __forceinline__ void mma16816(float* c, const uint32_t* a, uint32_t b0, uint32_t b1) {
    asm volatile("mma.sync.aligned.m16n8k16.row.col.f32.bf16.bf16.f32 "
        "{%0,%1,%2,%3}, {%4,%5,%6,%7}, {%8,%9}, {%0,%1,%2,%3};"
        : "+f"(c[0]), "+f"(c[1]), "+f"(c[2]), "+f"(c[3])
        : "r"(a[0]), "r"(a[1]), "r"(a[2]), "r"(a[3]), "r"(b0), "r"(b1));
}

// =============================================================================
// Weight transpose + bf16 RN-split kernels (batched over blockIdx.z).
// Body: W[K,N] fp32 -> hi/lo [N,K] bf16.
// =============================================================================
__device__ __forceinline__ void wsplit_body(const float* __restrict__ W,
                                            __nv_bfloat16* __restrict__ hi,
                                            __nv_bfloat16* __restrict__ lo,
                                            int K, int N, int k0, int n0,
                                            float t[32][33])
{
    const int tx = threadIdx.x & 31, ty = threadIdx.x >> 5;
    #pragma unroll
    for (int r = ty; r < 32; r += 8)
        t[r][tx] = W[(long long)(k0 + r) * N + n0 + tx];
    __syncthreads();
    #pragma unroll
    for (int r = ty; r < 32; r += 8) {
        float f = t[tx][r];
        __nv_bfloat16 hb = __float2bfloat16(f);
        long long o = (long long)(n0 + r) * K + k0 + tx;
        hi[o] = hb;
        lo[o] = __float2bfloat16(f - __bfloat162float(hb));
    }
}

// QKVO weights: z = layer*4 + which, each [D,D]
__global__ __launch_bounds__(256)
void wsplit_qkvo(const float* __restrict__ Wq, const float* __restrict__ Wk,
                 const float* __restrict__ Wv, const float* __restrict__ Wo,
                 __nv_bfloat16* __restrict__ hi, __nv_bfloat16* __restrict__ lo)
{
    __shared__ float t[32][33];
    const int z = blockIdx.z, l = z >> 2, w = z & 3;
    const float* W = (w == 0 ? Wq : w == 1 ? Wk : w == 2 ? Wv : Wo) + (size_t)l * WD_SZ;
    size_t ob = (size_t)l * LW_SZ + (size_t)w * WD_SZ;
    wsplit_body(W, hi + ob, lo + ob, D_, D_, blockIdx.y * 32, blockIdx.x * 32, t);
}

// W1: z = layer, [D,FF]
__global__ __launch_bounds__(256)
void wsplit_w1(const float* __restrict__ W1, __nv_bfloat16* __restrict__ hi,
               __nv_bfloat16* __restrict__ lo)
{
    __shared__ float t[32][33];
    const int l = blockIdx.z;
    size_t ob = (size_t)l * LW_SZ + 4 * WD_SZ;
    wsplit_body(W1 + (size_t)l * D_ * FF_, hi + ob, lo + ob, D_, FF_,
                blockIdx.y * 32, blockIdx.x * 32, t);
}

// W2: z = layer, [FF,D]
__global__ __launch_bounds__(256)
void wsplit_w2(const float* __restrict__ W2, __nv_bfloat16* __restrict__ hi,
               __nv_bfloat16* __restrict__ lo)
{
    __shared__ float t[32][33];
    const int l = blockIdx.z;
    size_t ob = (size_t)l * LW_SZ + 4 * WD_SZ + (size_t)D_ * FF_;
    wsplit_body(W2 + (size_t)l * FF_ * D_, hi + ob, lo + ob, FF_, D_,
                blockIdx.y * 32, blockIdx.x * 32, t);
}

// Wh: [D,V]
__global__ __launch_bounds__(256)
void wsplit_wh(const float* __restrict__ Wh, __nv_bfloat16* __restrict__ hi,
               __nv_bfloat16* __restrict__ lo)
{
    __shared__ float t[32][33];
    wsplit_body(Wh, hi, lo, D_, V_, blockIdx.y * 32, blockIdx.x * 32, t);
}

// concat per-layer qkv biases into [L][3072]
__global__ __launch_bounds__(1024)
void bconcat_kernel(const float* __restrict__ bq, const float* __restrict__ bk,
                    const float* __restrict__ bv, float* __restrict__ out)
{
    const int l = blockIdx.x, t = threadIdx.x;
    out[l * 3072 + t]        = bq[l * D_ + t];
    out[l * 3072 + 1024 + t] = bk[l * D_ + t];
    out[l * 3072 + 2048 + t] = bv[l * D_ + t];
}

// =============================================================================
// Pre-split bf16 GEMM — BK=64, 2-stage smem double buffer via LDG->reg->STS,
// ONE __syncthreads per chunk, occ 1 (registers ~170, no spills).
//   C = A(MxK) * B(KxN) + bias; A,B pre-split hi/lo bf16, k-contiguous.
// OUT: 0 = split bf16 out (C0=hi,C1=lo); 1 = gelu then split;
//      2 = +residual -> fp32 C0;        3 = fp32 C0.
// Segmented output (fused QKV): gc -> (gc>>segbits)*segstride + gr*ldc + (gc&mask)
// =============================================================================
#define TBM 128
#define TBN 128
#define TBK 64
#define TLDS (TBK + 8)                       // 72 halves
#define TASZ (TBM * TLDS)                    // 9216 elems per part
#define TSTG (4 * TASZ)                      // 36864 halves per stage
#define GEMM_SMEM (2 * TSTG * 2)             // 147456 bytes

template<int OUT>
__global__ __launch_bounds__(256, 1)
void gemm_ps(const __nv_bfloat16* __restrict__ Ahg, const __nv_bfloat16* __restrict__ Alg,
             const __nv_bfloat16* __restrict__ Bhg, const __nv_bfloat16* __restrict__ Blg,
             const float* __restrict__ bias, const float* __restrict__ res,
             void* __restrict__ C0v, void* __restrict__ C1v,
             int M, int N, int K, int lda, int ldb, int ldc,
             long long segstride, int segbits)
{
    constexpr int WM = 32, WN = 64;
    constexpr int MW = TBM / WM;             // 4
    constexpr int NW = TBN / WN;             // 2
    constexpr int MI = WM / 16, NI = WN / 16;

    extern __shared__ __align__(16) __nv_bfloat16 sm[];

    const int bm   = blockIdx.y * TBM;
    const int bn   = blockIdx.x * TBN;
    const int tid  = threadIdx.x;
    const int warp = tid >> 5;
    const int lane = tid & 31;
    const int wm   = (warp % MW) * WM;
    const int wn   = (warp / MW) * WN;
    const int nch  = K / TBK;

    // per-thread copy coordinates
    const int cm = tid >> 3;                 // row base 0..31 (stride 32)
    const int cq = (tid & 7) * 8;            // k offset in halves (16B)

    wmma::fragment<wmma::accumulator, 16, 16, 16, float> acc[MI][NI];
    #pragma unroll
    for (int i = 0; i < MI; i++)
        #pragma unroll
        for (int j = 0; j < NI; j++)
            wmma::fill_fragment(acc[i][j], 0.0f);

    uint4 ra[8], rb[8];                      // staging registers (64 regs)

    auto ldg = [&](int c) {
        const int k0 = c * TBK;
        #pragma unroll
        for (int p = 0; p < 4; ++p) {
            long long ga = (long long)(bm + cm + p * 32) * lda + k0 + cq;
            ra[p * 2]     = *(const uint4*)(Ahg + ga);
            ra[p * 2 + 1] = *(const uint4*)(Alg + ga);
            long long gb = (long long)(bn + cm + p * 32) * ldb + k0 + cq;
            rb[p * 2]     = *(const uint4*)(Bhg + gb);
            rb[p * 2 + 1] = *(const uint4*)(Blg + gb);
        }
    };
    auto sts = [&](int c) {
        __nv_bfloat16* st = sm + (c & 1) * TSTG;
        #pragma unroll
        for (int p = 0; p < 4; ++p) {
            int m = cm + p * 32;
            *(uint4*)(st + m * TLDS + cq)            = ra[p * 2];
            *(uint4*)(st + TASZ + m * TLDS + cq)     = ra[p * 2 + 1];
            *(uint4*)(st + 2 * TASZ + m * TLDS + cq) = rb[p * 2];
            *(uint4*)(st + 3 * TASZ + m * TLDS + cq) = rb[p * 2 + 1];
        }
    };

    ldg(0);
    for (int c = 0; c < nch; ++c) {
        sts(c);
        if (c + 1 < nch) ldg(c + 1);         // prefetch next chunk under this MMA
        __syncthreads();                     // single barrier per chunk

        const __nv_bfloat16* Ah = sm + (c & 1) * TSTG;
        const __nv_bfloat16* Al = Ah + TASZ;
        const __nv_bfloat16* Bh = Ah + 2 * TASZ;
        const __nv_bfloat16* Bl = Bh + TASZ;

        #pragma unroll
        for (int kk = 0; kk < TBK; kk += 16) {
            wmma::fragment<wmma::matrix_a, 16, 16, 16, __nv_bfloat16, wmma::row_major> ahi[MI], alo[MI];
            #pragma unroll
            for (int i = 0; i < MI; i++) {
                wmma::load_matrix_sync(ahi[i], Ah + (wm + i * 16) * TLDS + kk, TLDS);
                wmma::load_matrix_sync(alo[i], Al + (wm + i * 16) * TLDS + kk, TLDS);
            }
            #pragma unroll
            for (int j = 0; j < NI; j++) {
                wmma::fragment<wmma::matrix_b, 16, 16, 16, __nv_bfloat16, wmma::col_major> bhi, blo;
                wmma::load_matrix_sync(bhi, Bh + (wn + j * 16) * TLDS + kk, TLDS);
                wmma::load_matrix_sync(blo, Bl + (wn + j * 16) * TLDS + kk, TLDS);
                #pragma unroll
                for (int i = 0; i < MI; i++) {
                    wmma::mma_sync(acc[i][j], ahi[i], bhi, acc[i][j]);
                    wmma::mma_sync(acc[i][j], alo[i], bhi, acc[i][j]);
                    wmma::mma_sync(acc[i][j], ahi[i], blo, acc[i][j]);
                }
            }
        }
        // no trailing sync: sync#(c+1) separates MMA(c) from STS(c+2)
    }
    __syncthreads();                         // all MMA done before epilogue smem reuse

    // ---- epilogue: stage per-warp tile in (dead) smem, paired stores ----
    constexpr int LDS_T = WN + 4;
    float* stg = (float*)sm + (warp % MW) * (WM * LDS_T);
    const unsigned segmask = (segbits >= 30) ? 0xffffffffu : ((1u << segbits) - 1u);
    #pragma unroll
    for (int wave = 0; wave < NW; ++wave) {
        if ((warp / MW) == wave) {
            #pragma unroll
            for (int i = 0; i < MI; i++)
                #pragma unroll
                for (int j = 0; j < NI; j++)
                    wmma::store_matrix_sync(&stg[(i * 16) * LDS_T + j * 16], acc[i][j],
                                            LDS_T, wmma::mem_row_major);
            __syncwarp();
            for (int ii = lane; ii < WM * WN / 2; ii += 32) {
                int r  = ii / (WN / 2), c2 = (ii % (WN / 2)) * 2;
                int gr = bm + wm + r, gc = bn + wn + c2;
                float2 vv = *(float2*)&stg[r * LDS_T + c2];
                float2 bb = *(const float2*)&bias[gc];
                float a = vv.x + bb.x, b = vv.y + bb.y;
                long long caddr = (long long)((unsigned)gc >> segbits) * segstride
                                + (long long)gr * ldc + (gc & segmask);
                if constexpr (OUT == 1) { a = gelu_f(a); b = gelu_f(b); }
                if constexpr (OUT == 2) {
                    float2 rr = *(const float2*)&res[caddr];
                    *(float2*)((float*)C0v + caddr) = make_float2(a + rr.x, b + rr.y);
                } else if constexpr (OUT == 3) {
                    *(float2*)((float*)C0v + caddr) = make_float2(a, b);
                } else {
                    uint32_t h, l;
                    pack_split2(a, b, h, l);
                    *(uint32_t*)((__nv_bfloat16*)C0v + caddr) = h;
                    *(uint32_t*)((__nv_bfloat16*)C1v + caddr) = l;
                }
            }
        }
        __syncthreads();
    }
}

// =============================================================================
// Fused causal flash attention — pre-split bf16 Q,K,V in gmem, split O out.
// Grid: (T/128, B*H). 256 threads = 8 warps, each owns a 16-row Q band.
// =============================================================================
#define FA_LD 72
#define FA_SMEM 73728

__global__ __launch_bounds__(256, 2)
void fa_kernel(const __nv_bfloat16* __restrict__ qhg, const __nv_bfloat16* __restrict__ qlg,
               const __nv_bfloat16* __restrict__ khg, const __nv_bfloat16* __restrict__ klg,
               const __nv_bfloat16* __restrict__ vhg, const __nv_bfloat16* __restrict__ vlg,
               __nv_bfloat16* __restrict__ ohg, __nv_bfloat16* __restrict__ olg)
{
    const int bq = blockIdx.x, bh = blockIdx.y;
    const int b = bh / H_, hh = bh % H_;
    const int q0 = bq * 128;
    const int tid = threadIdx.x, warp = tid >> 5, lane = tid & 31;

    extern __shared__ __align__(16) char smraw[];
    __nv_bfloat16* Qh  = (__nv_bfloat16*)(smraw);
    __nv_bfloat16* Ql  = (__nv_bfloat16*)(smraw + 18432);
    __nv_bfloat16* Kh  = (__nv_bfloat16*)(smraw + 36864);
    __nv_bfloat16* Kl  = (__nv_bfloat16*)(smraw + 46080);
    __nv_bfloat16* Vth = (__nv_bfloat16*)(smraw + 55296);
    __nv_bfloat16* Vtl = (__nv_bfloat16*)(smraw + 64512);

    const long long qbase = ((long long)(b * T_ + q0)) * D_ + hh * DH_;
    const long long kvbase = ((long long)b * T_) * D_ + hh * DH_;

    // ---- stage Q (raw copies of pre-split bf16) ----
    #pragma unroll
    for (int p = 0; p < 4; ++p) {
        int i = tid + p * 256;
        int r = i >> 3, q = (i & 7) * 8;
        long long g = qbase + (long long)r * D_ + q;
        *(uint4*)(Qh + r * FA_LD + q) = *(const uint4*)(qhg + g);
        *(uint4*)(Ql + r * FA_LD + q) = *(const uint4*)(qlg + g);
    }

    const int rA  = 16 * warp + (lane >> 2);
    const int grA = q0 + rA;

    float mA = -1e30f, mB = -1e30f, lA = 0.f, lB = 0.f;
    float oacc[32];
    #pragma unroll
    for (int i = 0; i < 32; i++) oacc[i] = 0.f;

    const int ntiles = (q0 + 128) / 64;

    for (int t = 0; t < ntiles; ++t) {
        const int kv0 = t * 64;
        __syncthreads();

        // ---- stage K tile (raw copies) ----
        #pragma unroll
        for (int p = 0; p < 2; ++p) {
            int i = tid + p * 256;
            int r = i >> 3, q = (i & 7) * 8;
            long long g = kvbase + (long long)(kv0 + r) * D_ + q;
            *(uint4*)(Kh + r * FA_LD + q) = *(const uint4*)(khg + g);
            *(uint4*)(Kl + r * FA_LD + q) = *(const uint4*)(klg + g);
        }
        // ---- stage V transposed (bf16 scatter) ----
        #pragma unroll
        for (int p = 0; p < 2; ++p) {
            int i = tid + p * 256;
            int r = i & 63, q = (i >> 6) * 8;
            long long g = kvbase + (long long)(kv0 + r) * D_ + q;
            uint4 hv = *(const uint4*)(vhg + g);
            uint4 lv = *(const uint4*)(vlg + g);
            const __nv_bfloat16* hp = (const __nv_bfloat16*)&hv;
            const __nv_bfloat16* lp = (const __nv_bfloat16*)&lv;
            #pragma unroll
            for (int j = 0; j < 8; ++j) {
                Vth[(q + j) * FA_LD + r] = hp[j];
                Vtl[(q + j) * FA_LD + r] = lp[j];
            }
        }
        __syncthreads();

        // ---- S = Q K^T, 3-term split ----
        float sacc[32];
        #pragma unroll
        for (int i = 0; i < 32; i++) sacc[i] = 0.f;
        #pragma unroll
        for (int ks = 0; ks < 4; ++ks) {
            const int k0 = ks * 16 + (lane & 3) * 2;
            uint32_t ah[4], al[4];
            ah[0] = *(const uint32_t*)(Qh + rA * FA_LD + k0);
            ah[1] = *(const uint32_t*)(Qh + (rA + 8) * FA_LD + k0);
            ah[2] = *(const uint32_t*)(Qh + rA * FA_LD + k0 + 8);
            ah[3] = *(const uint32_t*)(Qh + (rA + 8) * FA_LD + k0 + 8);
            al[0] = *(const uint32_t*)(Ql + rA * FA_LD + k0);
            al[1] = *(const uint32_t*)(Ql + (rA + 8) * FA_LD + k0);
            al[2] = *(const uint32_t*)(Ql + rA * FA_LD + k0 + 8);
            al[3] = *(const uint32_t*)(Ql + (rA + 8) * FA_LD + k0 + 8);
            #pragma unroll
            for (int nt = 0; nt < 8; ++nt) {
                const int n = nt * 8 + (lane >> 2);
                uint32_t bh0 = *(const uint32_t*)(Kh + n * FA_LD + k0);
                uint32_t bh1 = *(const uint32_t*)(Kh + n * FA_LD + k0 + 8);
                uint32_t bl0 = *(const uint32_t*)(Kl + n * FA_LD + k0);
                uint32_t bl1 = *(const uint32_t*)(Kl + n * FA_LD + k0 + 8);
                mma16816(sacc + 4 * nt, ah, bh0, bh1);
                mma16816(sacc + 4 * nt, al, bh0, bh1);
                mma16816(sacc + 4 * nt, ah, bl0, bl1);
            }
        }
        // exact 1/sqrt(64) scale (power of two)
        #pragma unroll
        for (int i = 0; i < 32; i++) sacc[i] *= 0.125f;

        // ---- causal mask (diagonal tiles only) ----
        if (kv0 + 63 > grA) {
            #pragma unroll
            for (int nt = 0; nt < 8; ++nt) {
                const int c = kv0 + nt * 8 + (lane & 3) * 2;
                if (c     > grA)     sacc[4 * nt + 0] = -1e30f;
                if (c + 1 > grA)     sacc[4 * nt + 1] = -1e30f;
                if (c     > grA + 8) sacc[4 * nt + 2] = -1e30f;
                if (c + 1 > grA + 8) sacc[4 * nt + 3] = -1e30f;
            }
        }

        // ---- online softmax ----
        float mxA = -1e30f, mxB = -1e30f;
        #pragma unroll
        for (int nt = 0; nt < 8; ++nt) {
            mxA = fmaxf(mxA, fmaxf(sacc[4 * nt + 0], sacc[4 * nt + 1]));
            mxB = fmaxf(mxB, fmaxf(sacc[4 * nt + 2], sacc[4 * nt + 3]));
        }
        mxA = fmaxf(mxA, __shfl_xor_sync(0xffffffffu, mxA, 1));
        mxA = fmaxf(mxA, __shfl_xor_sync(0xffffffffu, mxA, 2));
        mxB = fmaxf(mxB, __shfl_xor_sync(0xffffffffu, mxB, 1));
        mxB = fmaxf(mxB, __shfl_xor_sync(0xffffffffu, mxB, 2));
        const float mAn = fmaxf(mA, mxA), mBn = fmaxf(mB, mxB);
        const float alA = exp2f((mA - mAn) * 1.44269504f);
        const float alB = exp2f((mB - mBn) * 1.44269504f);
        mA = mAn; mB = mBn;

        float sumA = 0.f, sumB = 0.f;
        #pragma unroll
        for (int nt = 0; nt < 8; ++nt) {
            sacc[4 * nt + 0] = exp2f((sacc[4 * nt + 0] - mAn) * 1.44269504f);
            sacc[4 * nt + 1] = exp2f((sacc[4 * nt + 1] - mAn) * 1.44269504f);
            sacc[4 * nt + 2] = exp2f((sacc[4 * nt + 2] - mBn) * 1.44269504f);
            sacc[4 * nt + 3] = exp2f((sacc[4 * nt + 3] - mBn) * 1.44269504f);
            sumA += sacc[4 * nt + 0] + sacc[4 * nt + 1];
            sumB += sacc[4 * nt + 2] + sacc[4 * nt + 3];
        }
        sumA += __shfl_xor_sync(0xffffffffu, sumA, 1);
        sumA += __shfl_xor_sync(0xffffffffu, sumA, 2);
        sumB += __shfl_xor_sync(0xffffffffu, sumB, 1);
        sumB += __shfl_xor_sync(0xffffffffu, sumB, 2);
        lA = lA * alA + sumA;
        lB = lB * alB + sumB;
        #pragma unroll
        for (int nt = 0; nt < 8; ++nt) {
            oacc[4 * nt + 0] *= alA;
            oacc[4 * nt + 1] *= alA;
            oacc[4 * nt + 2] *= alB;
            oacc[4 * nt + 3] *= alB;
        }

        // ---- O += P V ----
        #pragma unroll
        for (int ks = 0; ks < 4; ++ks) {
            const int u = 2 * ks, v2 = 2 * ks + 1;
            uint32_t pah[4], pal[4];
            pack_split2(sacc[4 * u + 0],  sacc[4 * u + 1],  pah[0], pal[0]);
            pack_split2(sacc[4 * u + 2],  sacc[4 * u + 3],  pah[1], pal[1]);
            pack_split2(sacc[4 * v2 + 0], sacc[4 * v2 + 1], pah[2], pal[2]);
            pack_split2(sacc[4 * v2 + 2], sacc[4 * v2 + 3], pah[3], pal[3]);
            const int k0 = ks * 16 + (lane & 3) * 2;
            #pragma unroll
            for (int nt = 0; nt < 8; ++nt) {
                const int n = nt * 8 + (lane >> 2);
                uint32_t bh0 = *(const uint32_t*)(Vth + n * FA_LD + k0);
                uint32_t bh1 = *(const uint32_t*)(Vth + n * FA_LD + k0 + 8);
                uint32_t bl0 = *(const uint32_t*)(Vtl + n * FA_LD + k0);
                uint32_t bl1 = *(const uint32_t*)(Vtl + n * FA_LD + k0 + 8);
                mma16816(oacc + 4 * nt, pah, bh0, bh1);
                mma16816(oacc + 4 * nt, pal, bh0, bh1);
                mma16816(oacc + 4 * nt, pah, bl0, bl1);
            }
        }
    }

    // ---- epilogue: O /= l, write split bf16 ----
    const float ilA = 1.0f / lA, ilB = 1.0f / lB;
    #pragma unroll
    for (int nt = 0; nt < 8; ++nt) {
        const int c = nt * 8 + (lane & 3) * 2;
        uint32_t h0, l0, h1, l1;
        pack_split2(oacc[4 * nt + 0] * ilA, oacc[4 * nt + 1] * ilA, h0, l0);
        pack_split2(oacc[4 * nt + 2] * ilB, oacc[4 * nt + 3] * ilB, h1, l1);
        long long g0 = qbase + (long long)rA * D_ + c;
        long long g1 = qbase + (long long)(rA + 8) * D_ + c;
        *(uint32_t*)(ohg + g0) = h0;
        *(uint32_t*)(olg + g0) = l0;
        *(uint32_t*)(ohg + g1) = h1;
        *(uint32_t*)(olg + g1) = l1;
    }
}

// ---------------- LayerNorm: fp32 in, split bf16 out ---------------------------
__global__ __launch_bounds__(256)
void ln_kernel(const float* __restrict__ x, const float* __restrict__ g,
               const float* __restrict__ b, __nv_bfloat16* __restrict__ oh,
               __nv_bfloat16* __restrict__ ol)
{
    __shared__ float shs[8], shs2[8], shbc[2];
    const int row = blockIdx.x;
    const float* xr = x + (long long)row * D_;
    const int t = threadIdx.x;
    float v[4]; float s = 0.f, s2 = 0.f;
    #pragma unroll
    for (int i = 0; i < 4; i++) { v[i] = xr[t + i * 256]; s += v[i]; s2 += v[i] * v[i]; }
    #pragma unroll
    for (int off = 16; off; off >>= 1) {
        s  += __shfl_xor_sync(0xffffffffu, s,  off);
        s2 += __shfl_xor_sync(0xffffffffu, s2, off);
    }
    if ((t & 31) == 0) { shs[t >> 5] = s; shs2[t >> 5] = s2; }
    __syncthreads();
    if (t < 32) {
        s  = (t < 8) ? shs[t]  : 0.f;
        s2 = (t < 8) ? shs2[t] : 0.f;
        #pragma unroll
        for (int off = 4; off; off >>= 1) {
            s  += __shfl_xor_sync(0xffffffffu, s,  off);
            s2 += __shfl_xor_sync(0xffffffffu, s2, off);
        }
        if (t == 0) {
            float mu = s * (1.0f / D_);
            shbc[0] = mu;
            shbc[1] = rsqrtf(s2 * (1.0f / D_) - mu * mu + 1e-5f);
        }
    }
    __syncthreads();
    const float mu = shbc[0], inv = shbc[1];
    #pragma unroll
    for (int i = 0; i < 4; i++) {
        int c = t + i * 256;
        float val = (v[i] - mu) * inv * g[c] + b[c];
        __nv_bfloat16 hb = __float2bfloat16(val);
        oh[(long long)row * D_ + c] = hb;
        ol[(long long)row * D_ + c] = __float2bfloat16(val - __bfloat162float(hb));
    }
}

// ---------------- embedding ---------------------------------------------------
__global__ __launch_bounds__(256)
void embed_kernel(const int* __restrict__ idx, const float* __restrict__ tok,
                  const float* __restrict__ pos, float* __restrict__ x)
{
    const int bt = blockIdx.x;
    const int tk = idx[bt];
    const int tt = bt % T_;
    const float* tr = tok + (long long)tk * D_;
    const float* pr = pos + (long long)tt * D_;
    float* xr = x + (long long)bt * D_;
    for (int i = threadIdx.x; i < D_; i += 256) xr[i] = tr[i] + pr[i];
}

// ---------------- host wrapper -------------------------------------------------
template<int OUT>
static void gemm(const __nv_bfloat16* Ah, const __nv_bfloat16* Al,
                 const __nv_bfloat16* Bh, const __nv_bfloat16* Bl,
                 const float* bias, const float* res, void* C0, void* C1,
                 int M, int N, int K, int lda, int ldb, int ldc,
                 long long segstride = 0, int segbits = 30)
{
    static bool init = false;
    if (!init) {
        cudaFuncSetAttribute(gemm_ps<OUT>, cudaFuncAttributeMaxDynamicSharedMemorySize, GEMM_SMEM);
        init = true;
    }
    dim3 grid(N / TBN, M / TBM, 1);
    gemm_ps<OUT><<<grid, 256, GEMM_SMEM>>>(Ah, Al, Bh, Bl, bias, res, C0, C1,
                                           M, N, K, lda, ldb, ldc, segstride, segbits);
}

extern "C" void kernel_launch(void* const* d_in, const int* in_sizes, int n_in,
                              void* d_out, int out_size)
{
    (void)in_sizes; (void)n_in; (void)out_size;
    const int*   idx   = (const int*)  d_in[0];
    const float* tok   = (const float*)d_in[1];
    const float* pos   = (const float*)d_in[2];
    const float* ln1g  = (const float*)d_in[3];
    const float* ln1b  = (const float*)d_in[4];
    const float* Wq    = (const float*)d_in[5];
    const float* bq    = (const float*)d_in[6];
    const float* Wk    = (const float*)d_in[7];
    const float* bk    = (const float*)d_in[8];
    const float* Wv    = (const float*)d_in[9];
    const float* bv    = (const float*)d_in[10];
    const float* Wo    = (const float*)d_in[11];
    const float* bo    = (const float*)d_in[12];
    const float* ln2g  = (const float*)d_in[13];
    const float* ln2b  = (const float*)d_in[14];
    const float* W1    = (const float*)d_in[15];
    const float* b1    = (const float*)d_in[16];
    const float* W2    = (const float*)d_in[17];
    const float* b2    = (const float*)d_in[18];
    const float* lnfg  = (const float*)d_in[19];
    const float* lnfb  = (const float*)d_in[20];
    const float* Wh    = (const float*)d_in[21];
    const float* bh    = (const float*)d_in[22];

    float* x;
    float* bqkv;
    __nv_bfloat16 *ah, *al, *whi, *wlo;
    cudaGetSymbolAddress((void**)&x,    g_x);
    cudaGetSymbolAddress((void**)&ah,   g_ah);
    cudaGetSymbolAddress((void**)&al,   g_al);
    cudaGetSymbolAddress((void**)&whi,  g_whi);
    cudaGetSymbolAddress((void**)&wlo,  g_wlo);
    cudaGetSymbolAddress((void**)&bqkv, g_bqkv);

    cudaFuncSetAttribute(fa_kernel, cudaFuncAttributeMaxDynamicSharedMemorySize, FA_SMEM);

    // activation sub-buffers (hi/lo pairs)
    __nv_bfloat16 *hh = ah,            *hl = al;
    __nv_bfloat16 *qh = ah + MD_,      *ql = al + MD_;
    __nv_bfloat16 *kh = ah + 2 * MD_,  *kl = al + 2 * MD_;
    __nv_bfloat16 *vh = ah + 3 * MD_,  *vl = al + 3 * MD_;
    __nv_bfloat16 *oh = ah + 4 * MD_,  *ol = al + 4 * MD_;
    __nv_bfloat16 *fh = ah + 5 * MD_,  *fl = al + 5 * MD_;

    // -------- batched weight transpose + split (4 launches) -------------------
    wsplit_qkvo<<<dim3(D_ / 32, D_ / 32, 4 * L_), 256>>>(Wq, Wk, Wv, Wo, whi, wlo);
    wsplit_w1  <<<dim3(FF_ / 32, D_ / 32, L_), 256>>>(W1, whi, wlo);
    wsplit_w2  <<<dim3(D_ / 32, FF_ / 32, L_), 256>>>(W2, whi, wlo);
    const size_t off_wh = (size_t)L_ * LW_SZ;
    wsplit_wh  <<<dim3(V_ / 32, D_ / 32), 256>>>(Wh, whi + off_wh, wlo + off_wh);
    bconcat_kernel<<<L_, 1024>>>(bq, bk, bv, bqkv);

    embed_kernel<<<M_, 256>>>(idx, tok, pos, x);

    for (int l = 0; l < L_; ++l) {
        size_t base = (size_t)l * LW_SZ;
        const __nv_bfloat16 *wqkvh = whi + base,        *wqkvl = wlo + base;   // fused [3072,1024]
        const __nv_bfloat16 *woh = whi + base + 3 * WD_SZ, *wol = wlo + base + 3 * WD_SZ;
        const __nv_bfloat16 *w1h = whi + base + 4 * WD_SZ,                      *w1l = wlo + base + 4 * WD_SZ;
        const __nv_bfloat16 *w2h = whi + base + 4 * WD_SZ + (size_t)D_ * FF_,   *w2l = wlo + base + 4 * WD_SZ + (size_t)D_ * FF_;

        // ln1 -> h (split)
        ln_kernel<<<M_, 256>>>(x, ln1g + (size_t)l * D_, ln1b + (size_t)l * D_, hh, hl);

        // fused q|k|v projection: N=3072, segmented output into q/k/v buffers
        gemm<0>(hh, hl, wqkvh, wqkvl, bqkv + (size_t)l * 3072, nullptr, qh, ql,
                M_, 3 * D_, D_, D_, D_, D_, (long long)MD_, 10);

        // fused causal attention: o = softmax(q k^T / 8) v  (split in/out)
        fa_kernel<<<dim3(T_ / 128, B_ * H_), 256, FA_SMEM>>>(qh, ql, kh, kl, vh, vl, oh, ol);

        // x = x + O @ Wo + bo  (fp32 residual)
        gemm<2>(oh, ol, woh, wol, bo + (size_t)l * D_, x, x, nullptr, M_, D_, D_, D_, D_, D_);

        // ln2 -> h (split)
        ln_kernel<<<M_, 256>>>(x, ln2g + (size_t)l * D_, ln2b + (size_t)l * D_, hh, hl);

        // ff = gelu(h @ W1 + b1) -> split
        gemm<1>(hh, hl, w1h, w1l, b1 + (size_t)l * FF_, nullptr, fh, fl, M_, FF_, D_, D_, D_, FF_);

        // x = x + ff @ W2 + b2
        gemm<2>(fh, fl, w2h, w2l, b2 + (size_t)l * D_, x, x, nullptr, M_, D_, FF_, FF_, FF_, D_);
    }

    // final LN + head (fp32 out)
    ln_kernel<<<M_, 256>>>(x, lnfg, lnfb, hh, hl);
    gemm<3>(hh, hl, whi + off_wh, wlo + off_wh, bh, nullptr, (float*)d_out, nullptr, M_, V_, D_, D_, D_, V_);
}

// round 15
// speedup vs baseline: 1.7938x; 1.7938x over previous
#include <cuda_runtime.h>
#include <cuda_bf16.h>
#include <mma.h>
#include <cfloat>
#include <cstdint>

using namespace nvcuda;

#define L_  8
#define D_  1024
#define H_  16
#define T_  1024
#define V_  2048
#define B_  8
#define DH_ 64
#define FF_ 4096
#define M_  (B_ * T_)   // 8192 rows
#define MD_ ((size_t)M_ * D_)   // 8,388,608
#define WD_SZ ((size_t)D_ * D_)
#define LW_SZ (4 * WD_SZ + (size_t)D_ * FF_ + (size_t)FF_ * D_)

// ---------------- scratch (device globals; no allocation allowed) -------------
__device__ float g_x [ MD_ ];                       // fp32 residual stream

// pre-split activations (hi/lo bf16): h | q | k | v | o | ff
#define ACT_TOT ((size_t)M_ * (5 * D_ + FF_))       // 75,497,472
__device__ __nv_bfloat16 g_ah[ACT_TOT];
__device__ __nv_bfloat16 g_al[ACT_TOT];

// Transposed + bf16-split weights: [N,K] K-major, hi and lo parts.
#define WTOT 102760448ULL
__device__ __nv_bfloat16 g_whi[WTOT];
__device__ __nv_bfloat16 g_wlo[WTOT];

// combined qkv bias per layer [L][3072]
__device__ float g_bqkv[L_ * 3 * D_];

// ---------------- helpers ----------------------------------------------------
__device__ __forceinline__ float gelu_f(float x) {
    return 0.5f * x * (1.0f + erff(x * 0.70710678118654752f));
}

// pack two floats into bf16x2 hi + residual lo
__device__ __forceinline__ void pack_split2(float x, float y, uint32_t& h, uint32_t& l) {
    asm("cvt.rn.bf16x2.f32 %0, %1, %2;" : "=r"(h) : "f"(y), "f"(x));
    float hx = __uint_as_float(h << 16);
    float hy = __uint_as_float(h & 0xffff0000u);
    asm("cvt.rn.bf16x2.f32 %0, %1, %2;" : "=r"(l) : "f"(y - hy), "f"(x - hx));
}

// raw bf16 mma m16n8k16
__device__ __forceinline__ void mma16816(float* c, const uint32_t* a, uint32_t b0, uint32_t b1) {
    asm volatile("mma.sync.aligned.m16n8k16.row.col.f32.bf16.bf16.f32 "
        "{%0,%1,%2,%3}, {%4,%5,%6,%7}, {%8,%9}, {%0,%1,%2,%3};"
        : "+f"(c[0]), "+f"(c[1]), "+f"(c[2]), "+f"(c[3])
        : "r"(a[0]), "r"(a[1]), "r"(a[2]), "r"(a[3]), "r"(b0), "r"(b1));
}

// =============================================================================
// Weight transpose + bf16 RN-split kernels (batched over blockIdx.z).
// Body: W[K,N] fp32 -> hi/lo [N,K] bf16.
// =============================================================================
__device__ __forceinline__ void wsplit_body(const float* __restrict__ W,
                                            __nv_bfloat16* __restrict__ hi,
                                            __nv_bfloat16* __restrict__ lo,
                                            int K, int N, int k0, int n0,
                                            float t[32][33])
{
    const int tx = threadIdx.x & 31, ty = threadIdx.x >> 5;
    #pragma unroll
    for (int r = ty; r < 32; r += 8)
        t[r][tx] = W[(long long)(k0 + r) * N + n0 + tx];
    __syncthreads();
    #pragma unroll
    for (int r = ty; r < 32; r += 8) {
        float f = t[tx][r];
        __nv_bfloat16 hb = __float2bfloat16(f);
        long long o = (long long)(n0 + r) * K + k0 + tx;
        hi[o] = hb;
        lo[o] = __float2bfloat16(f - __bfloat162float(hb));
    }
}

// QKVO weights: z = layer*4 + which, each [D,D]
__global__ __launch_bounds__(256)
void wsplit_qkvo(const float* __restrict__ Wq, const float* __restrict__ Wk,
                 const float* __restrict__ Wv, const float* __restrict__ Wo,
                 __nv_bfloat16* __restrict__ hi, __nv_bfloat16* __restrict__ lo)
{
    __shared__ float t[32][33];
    const int z = blockIdx.z, l = z >> 2, w = z & 3;
    const float* W = (w == 0 ? Wq : w == 1 ? Wk : w == 2 ? Wv : Wo) + (size_t)l * WD_SZ;
    size_t ob = (size_t)l * LW_SZ + (size_t)w * WD_SZ;
    wsplit_body(W, hi + ob, lo + ob, D_, D_, blockIdx.y * 32, blockIdx.x * 32, t);
}

// W1: z = layer, [D,FF]
__global__ __launch_bounds__(256)
void wsplit_w1(const float* __restrict__ W1, __nv_bfloat16* __restrict__ hi,
               __nv_bfloat16* __restrict__ lo)
{
    __shared__ float t[32][33];
    const int l = blockIdx.z;
    size_t ob = (size_t)l * LW_SZ + 4 * WD_SZ;
    wsplit_body(W1 + (size_t)l * D_ * FF_, hi + ob, lo + ob, D_, FF_,
                blockIdx.y * 32, blockIdx.x * 32, t);
}

// W2: z = layer, [FF,D]
__global__ __launch_bounds__(256)
void wsplit_w2(const float* __restrict__ W2, __nv_bfloat16* __restrict__ hi,
               __nv_bfloat16* __restrict__ lo)
{
    __shared__ float t[32][33];
    const int l = blockIdx.z;
    size_t ob = (size_t)l * LW_SZ + 4 * WD_SZ + (size_t)D_ * FF_;
    wsplit_body(W2 + (size_t)l * FF_ * D_, hi + ob, lo + ob, FF_, D_,
                blockIdx.y * 32, blockIdx.x * 32, t);
}

// Wh: [D,V]
__global__ __launch_bounds__(256)
void wsplit_wh(const float* __restrict__ Wh, __nv_bfloat16* __restrict__ hi,
               __nv_bfloat16* __restrict__ lo)
{
    __shared__ float t[32][33];
    wsplit_body(Wh, hi, lo, D_, V_, blockIdx.y * 32, blockIdx.x * 32, t);
}

// concat per-layer qkv biases into [L][3072]
__global__ __launch_bounds__(1024)
void bconcat_kernel(const float* __restrict__ bq, const float* __restrict__ bk,
                    const float* __restrict__ bv, float* __restrict__ out)
{
    const int l = blockIdx.x, t = threadIdx.x;
    out[l * 3072 + t]        = bq[l * D_ + t];
    out[l * 3072 + 1024 + t] = bk[l * D_ + t];
    out[l * 3072 + 2048 + t] = bv[l * D_ + t];
}

// =============================================================================
// Pre-split bf16 GEMM — BK=64, single-buffered raw-copy staging, occ 2 (= R13)
// + wave-anti-phase chunk rotation: co-resident CTAs (bid, bid+148) process
//   k-chunks starting nch/2 apart so their staging phases interleave with the
//   partner's MMA phases instead of colliding.
// OUT: 0 = split bf16 out; 1 = gelu+split; 2 = +residual fp32; 3 = fp32.
// =============================================================================
#define TBM 128
#define TBN 128
#define TBK 64
#define TLDS (TBK + 8)                       // 72 halves
#define TASZ (TBM * TLDS)                    // 9216 elems per part
#define GEMM_SMEM (4 * TASZ * 2)             // 73728 bytes

template<int OUT>
__global__ __launch_bounds__(256, 2)
void gemm_ps(const __nv_bfloat16* __restrict__ Ahg, const __nv_bfloat16* __restrict__ Alg,
             const __nv_bfloat16* __restrict__ Bhg, const __nv_bfloat16* __restrict__ Blg,
             const float* __restrict__ bias, const float* __restrict__ res,
             void* __restrict__ C0v, void* __restrict__ C1v,
             int M, int N, int K, int lda, int ldb, int ldc,
             long long segstride, int segbits)
{
    constexpr int WM = 32, WN = 64;
    constexpr int MW = TBM / WM;             // 4
    constexpr int NW = TBN / WN;             // 2
    constexpr int MI = WM / 16, NI = WN / 16;

    extern __shared__ __align__(16) __nv_bfloat16 sm[];
    __nv_bfloat16* Ah = sm;
    __nv_bfloat16* Al = Ah + TASZ;
    __nv_bfloat16* Bh = Al + TASZ;
    __nv_bfloat16* Bl = Bh + TASZ;

    const int bm   = blockIdx.y * TBM;
    const int bn   = blockIdx.x * TBN;
    const int tid  = threadIdx.x;
    const int warp = tid >> 5;
    const int lane = tid & 31;
    const int wm   = (warp % MW) * WM;
    const int wn   = (warp / MW) * WN;
    const int nch  = K / TBK;

    // anti-phase: wave-1 partner (bid+148) starts halfway through the chunk ring
    const int bid   = blockIdx.y * gridDim.x + blockIdx.x;
    const int phase = ((bid / 148) & 1) ? (nch >> 1) : 0;

    wmma::fragment<wmma::accumulator, 16, 16, 16, float> acc[MI][NI];
    #pragma unroll
    for (int i = 0; i < MI; i++)
        #pragma unroll
        for (int j = 0; j < NI; j++)
            wmma::fill_fragment(acc[i][j], 0.0f);

    for (int cc = 0; cc < nch; ++cc) {
        int c = cc + phase;
        if (c >= nch) c -= nch;
        const int k0 = c * TBK;

        // ---- stage A & B: raw uint4 copies of pre-split operands ----
        #pragma unroll
        for (int p = 0; p < 4; ++p) {                 // A: 128 rows x 64 halves
            int i = tid + p * 256;
            int m = i >> 3, q = (i & 7) * 8;
            long long ga = (long long)(bm + m) * lda + k0 + q;
            *(uint4*)(Ah + m * TLDS + q) = *(const uint4*)(Ahg + ga);
            *(uint4*)(Al + m * TLDS + q) = *(const uint4*)(Alg + ga);
        }
        #pragma unroll
        for (int p = 0; p < 4; ++p) {                 // B: 128 rows x 64 halves
            int i = tid + p * 256;
            int n = i >> 3, q = (i & 7) * 8;
            long long gb = (long long)(bn + n) * ldb + k0 + q;
            *(uint4*)(Bh + n * TLDS + q) = *(const uint4*)(Bhg + gb);
            *(uint4*)(Bl + n * TLDS + q) = *(const uint4*)(Blg + gb);
        }
        __syncthreads();

        // ---- MMA mainloop: pure LDSM + HMMA ----
        #pragma unroll
        for (int kk = 0; kk < TBK; kk += 16) {
            wmma::fragment<wmma::matrix_a, 16, 16, 16, __nv_bfloat16, wmma::row_major> ahi[MI], alo[MI];
            #pragma unroll
            for (int i = 0; i < MI; i++) {
                wmma::load_matrix_sync(ahi[i], Ah + (wm + i * 16) * TLDS + kk, TLDS);
                wmma::load_matrix_sync(alo[i], Al + (wm + i * 16) * TLDS + kk, TLDS);
            }
            #pragma unroll
            for (int j = 0; j < NI; j++) {
                wmma::fragment<wmma::matrix_b, 16, 16, 16, __nv_bfloat16, wmma::col_major> bhi, blo;
                wmma::load_matrix_sync(bhi, Bh + (wn + j * 16) * TLDS + kk, TLDS);
                wmma::load_matrix_sync(blo, Bl + (wn + j * 16) * TLDS + kk, TLDS);
                #pragma unroll
                for (int i = 0; i < MI; i++) {
                    wmma::mma_sync(acc[i][j], ahi[i], bhi, acc[i][j]);
                    wmma::mma_sync(acc[i][j], alo[i], bhi, acc[i][j]);
                    wmma::mma_sync(acc[i][j], ahi[i], blo, acc[i][j]);
                }
            }
        }
        __syncthreads();
    }

    // ---- epilogue: stage per-warp tile in (dead) smem, paired stores ----
    constexpr int LDS_T = WN + 4;
    float* stg = (float*)sm + (warp % MW) * (WM * LDS_T);
    const unsigned segmask = (segbits >= 30) ? 0xffffffffu : ((1u << segbits) - 1u);
    #pragma unroll
    for (int wave = 0; wave < NW; ++wave) {
        if ((warp / MW) == wave) {
            #pragma unroll
            for (int i = 0; i < MI; i++)
                #pragma unroll
                for (int j = 0; j < NI; j++)
                    wmma::store_matrix_sync(&stg[(i * 16) * LDS_T + j * 16], acc[i][j],
                                            LDS_T, wmma::mem_row_major);
            __syncwarp();
            for (int ii = lane; ii < WM * WN / 2; ii += 32) {
                int r  = ii / (WN / 2), c2 = (ii % (WN / 2)) * 2;
                int gr = bm + wm + r, gc = bn + wn + c2;
                float2 vv = *(float2*)&stg[r * LDS_T + c2];
                float2 bb = *(const float2*)&bias[gc];
                float a = vv.x + bb.x, b = vv.y + bb.y;
                long long caddr = (long long)((unsigned)gc >> segbits) * segstride
                                + (long long)gr * ldc + (gc & segmask);
                if constexpr (OUT == 1) { a = gelu_f(a); b = gelu_f(b); }
                if constexpr (OUT == 2) {
                    float2 rr = *(const float2*)&res[caddr];
                    *(float2*)((float*)C0v + caddr) = make_float2(a + rr.x, b + rr.y);
                } else if constexpr (OUT == 3) {
                    *(float2*)((float*)C0v + caddr) = make_float2(a, b);
                } else {
                    uint32_t h, l;
                    pack_split2(a, b, h, l);
                    *(uint32_t*)((__nv_bfloat16*)C0v + caddr) = h;
                    *(uint32_t*)((__nv_bfloat16*)C1v + caddr) = l;
                }
            }
        }
        __syncthreads();
    }
}

// =============================================================================
// Fused causal flash attention — pre-split bf16 Q,K,V in gmem, split O out.
// Grid: (T/128, B*H). 256 threads = 8 warps, each owns a 16-row Q band.
// Warps whose rows are entirely above the diagonal skip compute on that tile
// (exactly equivalent: all-masked tile contributes alpha=1, sum=0).
// =============================================================================
#define FA_LD 72
#define FA_SMEM 73728

__global__ __launch_bounds__(256, 2)
void fa_kernel(const __nv_bfloat16* __restrict__ qhg, const __nv_bfloat16* __restrict__ qlg,
               const __nv_bfloat16* __restrict__ khg, const __nv_bfloat16* __restrict__ klg,
               const __nv_bfloat16* __restrict__ vhg, const __nv_bfloat16* __restrict__ vlg,
               __nv_bfloat16* __restrict__ ohg, __nv_bfloat16* __restrict__ olg)
{
    const int bq = blockIdx.x, bh = blockIdx.y;
    const int b = bh / H_, hh = bh % H_;
    const int q0 = bq * 128;
    const int tid = threadIdx.x, warp = tid >> 5, lane = tid & 31;

    extern __shared__ __align__(16) char smraw[];
    __nv_bfloat16* Qh  = (__nv_bfloat16*)(smraw);
    __nv_bfloat16* Ql  = (__nv_bfloat16*)(smraw + 18432);
    __nv_bfloat16* Kh  = (__nv_bfloat16*)(smraw + 36864);
    __nv_bfloat16* Kl  = (__nv_bfloat16*)(smraw + 46080);
    __nv_bfloat16* Vth = (__nv_bfloat16*)(smraw + 55296);
    __nv_bfloat16* Vtl = (__nv_bfloat16*)(smraw + 64512);

    const long long qbase = ((long long)(b * T_ + q0)) * D_ + hh * DH_;
    const long long kvbase = ((long long)b * T_) * D_ + hh * DH_;

    // ---- stage Q (raw copies of pre-split bf16) ----
    #pragma unroll
    for (int p = 0; p < 4; ++p) {
        int i = tid + p * 256;
        int r = i >> 3, q = (i & 7) * 8;
        long long g = qbase + (long long)r * D_ + q;
        *(uint4*)(Qh + r * FA_LD + q) = *(const uint4*)(qhg + g);
        *(uint4*)(Ql + r * FA_LD + q) = *(const uint4*)(qlg + g);
    }

    const int rA  = 16 * warp + (lane >> 2);
    const int grA = q0 + rA;

    float mA = -1e30f, mB = -1e30f, lA = 0.f, lB = 0.f;
    float oacc[32];
    #pragma unroll
    for (int i = 0; i < 32; i++) oacc[i] = 0.f;

    const int ntiles = (q0 + 128) / 64;

    for (int t = 0; t < ntiles; ++t) {
        const int kv0 = t * 64;
        __syncthreads();

        // ---- stage K tile (raw copies) ----
        #pragma unroll
        for (int p = 0; p < 2; ++p) {
            int i = tid + p * 256;
            int r = i >> 3, q = (i & 7) * 8;
            long long g = kvbase + (long long)(kv0 + r) * D_ + q;
            *(uint4*)(Kh + r * FA_LD + q) = *(const uint4*)(khg + g);
            *(uint4*)(Kl + r * FA_LD + q) = *(const uint4*)(klg + g);
        }
        // ---- stage V transposed (bf16 scatter) ----
        #pragma unroll
        for (int p = 0; p < 2; ++p) {
            int i = tid + p * 256;
            int r = i & 63, q = (i >> 6) * 8;
            long long g = kvbase + (long long)(kv0 + r) * D_ + q;
            uint4 hv = *(const uint4*)(vhg + g);
            uint4 lv = *(const uint4*)(vlg + g);
            const __nv_bfloat16* hp = (const __nv_bfloat16*)&hv;
            const __nv_bfloat16* lp = (const __nv_bfloat16*)&lv;
            #pragma unroll
            for (int j = 0; j < 8; ++j) {
                Vth[(q + j) * FA_LD + r] = hp[j];
                Vtl[(q + j) * FA_LD + r] = lp[j];
            }
        }
        __syncthreads();

        // whole-warp skip: tile entirely above the diagonal for this warp's rows
        if (kv0 > grA + 8) continue;

        // ---- S = Q K^T, 3-term split ----
        float sacc[32];
        #pragma unroll
        for (int i = 0; i < 32; i++) sacc[i] = 0.f;
        #pragma unroll
        for (int ks = 0; ks < 4; ++ks) {
            const int k0 = ks * 16 + (lane & 3) * 2;
            uint32_t ah[4], al[4];
            ah[0] = *(const uint32_t*)(Qh + rA * FA_LD + k0);
            ah[1] = *(const uint32_t*)(Qh + (rA + 8) * FA_LD + k0);
            ah[2] = *(const uint32_t*)(Qh + rA * FA_LD + k0 + 8);
            ah[3] = *(const uint32_t*)(Qh + (rA + 8) * FA_LD + k0 + 8);
            al[0] = *(const uint32_t*)(Ql + rA * FA_LD + k0);
            al[1] = *(const uint32_t*)(Ql + (rA + 8) * FA_LD + k0);
            al[2] = *(const uint32_t*)(Ql + rA * FA_LD + k0 + 8);
            al[3] = *(const uint32_t*)(Ql + (rA + 8) * FA_LD + k0 + 8);
            #pragma unroll
            for (int nt = 0; nt < 8; ++nt) {
                const int n = nt * 8 + (lane >> 2);
                uint32_t bh0 = *(const uint32_t*)(Kh + n * FA_LD + k0);
                uint32_t bh1 = *(const uint32_t*)(Kh + n * FA_LD + k0 + 8);
                uint32_t bl0 = *(const uint32_t*)(Kl + n * FA_LD + k0);
                uint32_t bl1 = *(const uint32_t*)(Kl + n * FA_LD + k0 + 8);
                mma16816(sacc + 4 * nt, ah, bh0, bh1);
                mma16816(sacc + 4 * nt, al, bh0, bh1);
                mma16816(sacc + 4 * nt, ah, bl0, bl1);
            }
        }
        // exact 1/sqrt(64) scale (power of two)
        #pragma unroll
        for (int i = 0; i < 32; i++) sacc[i] *= 0.125f;

        // ---- causal mask (diagonal tiles only) ----
        if (kv0 + 63 > grA) {
            #pragma unroll
            for (int nt = 0; nt < 8; ++nt) {
                const int c = kv0 + nt * 8 + (lane & 3) * 2;
                if (c     > grA)     sacc[4 * nt + 0] = -1e30f;
                if (c + 1 > grA)     sacc[4 * nt + 1] = -1e30f;
                if (c     > grA + 8) sacc[4 * nt + 2] = -1e30f;
                if (c + 1 > grA + 8) sacc[4 * nt + 3] = -1e30f;
            }
        }

        // ---- online softmax ----
        float mxA = -1e30f, mxB = -1e30f;
        #pragma unroll
        for (int nt = 0; nt < 8; ++nt) {
            mxA = fmaxf(mxA, fmaxf(sacc[4 * nt + 0], sacc[4 * nt + 1]));
            mxB = fmaxf(mxB, fmaxf(sacc[4 * nt + 2], sacc[4 * nt + 3]));
        }
        mxA = fmaxf(mxA, __shfl_xor_sync(0xffffffffu, mxA, 1));
        mxA = fmaxf(mxA, __shfl_xor_sync(0xffffffffu, mxA, 2));
        mxB = fmaxf(mxB, __shfl_xor_sync(0xffffffffu, mxB, 1));
        mxB = fmaxf(mxB, __shfl_xor_sync(0xffffffffu, mxB, 2));
        const float mAn = fmaxf(mA, mxA), mBn = fmaxf(mB, mxB);
        const float alA = exp2f((mA - mAn) * 1.44269504f);
        const float alB = exp2f((mB - mBn) * 1.44269504f);
        mA = mAn; mB = mBn;

        float sumA = 0.f, sumB = 0.f;
        #pragma unroll
        for (int nt = 0; nt < 8; ++nt) {
            sacc[4 * nt + 0] = exp2f((sacc[4 * nt + 0] - mAn) * 1.44269504f);
            sacc[4 * nt + 1] = exp2f((sacc[4 * nt + 1] - mAn) * 1.44269504f);
            sacc[4 * nt + 2] = exp2f((sacc[4 * nt + 2] - mBn) * 1.44269504f);
            sacc[4 * nt + 3] = exp2f((sacc[4 * nt + 3] - mBn) * 1.44269504f);
            sumA += sacc[4 * nt + 0] + sacc[4 * nt + 1];
            sumB += sacc[4 * nt + 2] + sacc[4 * nt + 3];
        }
        sumA += __shfl_xor_sync(0xffffffffu, sumA, 1);
        sumA += __shfl_xor_sync(0xffffffffu, sumA, 2);
        sumB += __shfl_xor_sync(0xffffffffu, sumB, 1);
        sumB += __shfl_xor_sync(0xffffffffu, sumB, 2);
        lA = lA * alA + sumA;
        lB = lB * alB + sumB;
        #pragma unroll
        for (int nt = 0; nt < 8; ++nt) {
            oacc[4 * nt + 0] *= alA;
            oacc[4 * nt + 1] *= alA;
            oacc[4 * nt + 2] *= alB;
            oacc[4 * nt + 3] *= alB;
        }

        // ---- O += P V ----
        #pragma unroll
        for (int ks = 0; ks < 4; ++ks) {
            const int u = 2 * ks, v2 = 2 * ks + 1;
            uint32_t pah[4], pal[4];
            pack_split2(sacc[4 * u + 0],  sacc[4 * u + 1],  pah[0], pal[0]);
            pack_split2(sacc[4 * u + 2],  sacc[4 * u + 3],  pah[1], pal[1]);
            pack_split2(sacc[4 * v2 + 0], sacc[4 * v2 + 1], pah[2], pal[2]);
            pack_split2(sacc[4 * v2 + 2], sacc[4 * v2 + 3], pah[3], pal[3]);
            const int k0 = ks * 16 + (lane & 3) * 2;
            #pragma unroll
            for (int nt = 0; nt < 8; ++nt) {
                const int n = nt * 8 + (lane >> 2);
                uint32_t bh0 = *(const uint32_t*)(Vth + n * FA_LD + k0);
                uint32_t bh1 = *(const uint32_t*)(Vth + n * FA_LD + k0 + 8);
                uint32_t bl0 = *(const uint32_t*)(Vtl + n * FA_LD + k0);
                uint32_t bl1 = *(const uint32_t*)(Vtl + n * FA_LD + k0 + 8);
                mma16816(oacc + 4 * nt, pah, bh0, bh1);
                mma16816(oacc + 4 * nt, pal, bh0, bh1);
                mma16816(oacc + 4 * nt, pah, bl0, bl1);
            }
        }
    }

    // ---- epilogue: O /= l, write split bf16 ----
    const float ilA = 1.0f / lA, ilB = 1.0f / lB;
    #pragma unroll
    for (int nt = 0; nt < 8; ++nt) {
        const int c = nt * 8 + (lane & 3) * 2;
        uint32_t h0, l0, h1, l1;
        pack_split2(oacc[4 * nt + 0] * ilA, oacc[4 * nt + 1] * ilA, h0, l0);
        pack_split2(oacc[4 * nt + 2] * ilB, oacc[4 * nt + 3] * ilB, h1, l1);
        long long g0 = qbase + (long long)rA * D_ + c;
        long long g1 = qbase + (long long)(rA + 8) * D_ + c;
        *(uint32_t*)(ohg + g0) = h0;
        *(uint32_t*)(olg + g0) = l0;
        *(uint32_t*)(ohg + g1) = h1;
        *(uint32_t*)(olg + g1) = l1;
    }
}

// ---------------- LayerNorm: fp32 in, split bf16 out ---------------------------
__global__ __launch_bounds__(256)
void ln_kernel(const float* __restrict__ x, const float* __restrict__ g,
               const float* __restrict__ b, __nv_bfloat16* __restrict__ oh,
               __nv_bfloat16* __restrict__ ol)
{
    __shared__ float shs[8], shs2[8], shbc[2];
    const int row = blockIdx.x;
    const float* xr = x + (long long)row * D_;
    const int t = threadIdx.x;
    float v[4]; float s = 0.f, s2 = 0.f;
    #pragma unroll
    for (int i = 0; i < 4; i++) { v[i] = xr[t + i * 256]; s += v[i]; s2 += v[i] * v[i]; }
    #pragma unroll
    for (int off = 16; off; off >>= 1) {
        s  += __shfl_xor_sync(0xffffffffu, s,  off);
        s2 += __shfl_xor_sync(0xffffffffu, s2, off);
    }
    if ((t & 31) == 0) { shs[t >> 5] = s; shs2[t >> 5] = s2; }
    __syncthreads();
    if (t < 32) {
        s  = (t < 8) ? shs[t]  : 0.f;
        s2 = (t < 8) ? shs2[t] : 0.f;
        #pragma unroll
        for (int off = 4; off; off >>= 1) {
            s  += __shfl_xor_sync(0xffffffffu, s,  off);
            s2 += __shfl_xor_sync(0xffffffffu, s2, off);
        }
        if (t == 0) {
            float mu = s * (1.0f / D_);
            shbc[0] = mu;
            shbc[1] = rsqrtf(s2 * (1.0f / D_) - mu * mu + 1e-5f);
        }
    }
    __syncthreads();
    const float mu = shbc[0], inv = shbc[1];
    #pragma unroll
    for (int i = 0; i < 4; i++) {
        int c = t + i * 256;
        float val = (v[i] - mu) * inv * g[c] + b[c];
        __nv_bfloat16 hb = __float2bfloat16(val);
        oh[(long long)row * D_ + c] = hb;
        ol[(long long)row * D_ + c] = __float2bfloat16(val - __bfloat162float(hb));
    }
}

// ---------------- embedding ---------------------------------------------------
__global__ __launch_bounds__(256)
void embed_kernel(const int* __restrict__ idx, const float* __restrict__ tok,
                  const float* __restrict__ pos, float* __restrict__ x)
{
    const int bt = blockIdx.x;
    const int tk = idx[bt];
    const int tt = bt % T_;
    const float* tr = tok + (long long)tk * D_;
    const float* pr = pos + (long long)tt * D_;
    float* xr = x + (long long)bt * D_;
    for (int i = threadIdx.x; i < D_; i += 256) xr[i] = tr[i] + pr[i];
}

// ---------------- host wrapper -------------------------------------------------
template<int OUT>
static void gemm(const __nv_bfloat16* Ah, const __nv_bfloat16* Al,
                 const __nv_bfloat16* Bh, const __nv_bfloat16* Bl,
                 const float* bias, const float* res, void* C0, void* C1,
                 int M, int N, int K, int lda, int ldb, int ldc,
                 long long segstride = 0, int segbits = 30)
{
    static bool init = false;
    if (!init) {
        cudaFuncSetAttribute(gemm_ps<OUT>, cudaFuncAttributeMaxDynamicSharedMemorySize, GEMM_SMEM);
        init = true;
    }
    dim3 grid(N / TBN, M / TBM, 1);
    gemm_ps<OUT><<<grid, 256, GEMM_SMEM>>>(Ah, Al, Bh, Bl, bias, res, C0, C1,
                                           M, N, K, lda, ldb, ldc, segstride, segbits);
}

extern "C" void kernel_launch(void* const* d_in, const int* in_sizes, int n_in,
                              void* d_out, int out_size)
{
    (void)in_sizes; (void)n_in; (void)out_size;
    const int*   idx   = (const int*)  d_in[0];
    const float* tok   = (const float*)d_in[1];
    const float* pos   = (const float*)d_in[2];
    const float* ln1g  = (const float*)d_in[3];
    const float* ln1b  = (const float*)d_in[4];
    const float* Wq    = (const float*)d_in[5];
    const float* bq    = (const float*)d_in[6];
    const float* Wk    = (const float*)d_in[7];
    const float* bk    = (const float*)d_in[8];
    const float* Wv    = (const float*)d_in[9];
    const float* bv    = (const float*)d_in[10];
    const float* Wo    = (const float*)d_in[11];
    const float* bo    = (const float*)d_in[12];
    const float* ln2g  = (const float*)d_in[13];
    const float* ln2b  = (const float*)d_in[14];
    const float* W1    = (const float*)d_in[15];
    const float* b1    = (const float*)d_in[16];
    const float* W2    = (const float*)d_in[17];
    const float* b2    = (const float*)d_in[18];
    const float* lnfg  = (const float*)d_in[19];
    const float* lnfb  = (const float*)d_in[20];
    const float* Wh    = (const float*)d_in[21];
    const float* bh    = (const float*)d_in[22];

    float* x;
    float* bqkv;
    __nv_bfloat16 *ah, *al, *whi, *wlo;
    cudaGetSymbolAddress((void**)&x,    g_x);
    cudaGetSymbolAddress((void**)&ah,   g_ah);
    cudaGetSymbolAddress((void**)&al,   g_al);
    cudaGetSymbolAddress((void**)&whi,  g_whi);
    cudaGetSymbolAddress((void**)&wlo,  g_wlo);
    cudaGetSymbolAddress((void**)&bqkv, g_bqkv);

    cudaFuncSetAttribute(fa_kernel, cudaFuncAttributeMaxDynamicSharedMemorySize, FA_SMEM);

    // activation sub-buffers (hi/lo pairs)
    __nv_bfloat16 *hh = ah,            *hl = al;
    __nv_bfloat16 *qh = ah + MD_,      *ql = al + MD_;
    __nv_bfloat16 *kh = ah + 2 * MD_,  *kl = al + 2 * MD_;
    __nv_bfloat16 *vh = ah + 3 * MD_,  *vl = al + 3 * MD_;
    __nv_bfloat16 *oh = ah + 4 * MD_,  *ol = al + 4 * MD_;
    __nv_bfloat16 *fh = ah + 5 * MD_,  *fl = al + 5 * MD_;

    // -------- batched weight transpose + split (4 launches) -------------------
    wsplit_qkvo<<<dim3(D_ / 32, D_ / 32, 4 * L_), 256>>>(Wq, Wk, Wv, Wo, whi, wlo);
    wsplit_w1  <<<dim3(FF_ / 32, D_ / 32, L_), 256>>>(W1, whi, wlo);
    wsplit_w2  <<<dim3(D_ / 32, FF_ / 32, L_), 256>>>(W2, whi, wlo);
    const size_t off_wh = (size_t)L_ * LW_SZ;
    wsplit_wh  <<<dim3(V_ / 32, D_ / 32), 256>>>(Wh, whi + off_wh, wlo + off_wh);
    bconcat_kernel<<<L_, 1024>>>(bq, bk, bv, bqkv);

    embed_kernel<<<M_, 256>>>(idx, tok, pos, x);

    for (int l = 0; l < L_; ++l) {
        size_t base = (size_t)l * LW_SZ;
        const __nv_bfloat16 *wqkvh = whi + base,        *wqkvl = wlo + base;   // fused [3072,1024]
        const __nv_bfloat16 *woh = whi + base + 3 * WD_SZ, *wol = wlo + base + 3 * WD_SZ;
        const __nv_bfloat16 *w1h = whi + base + 4 * WD_SZ,                      *w1l = wlo + base + 4 * WD_SZ;
        const __nv_bfloat16 *w2h = whi + base + 4 * WD_SZ + (size_t)D_ * FF_,   *w2l = wlo + base + 4 * WD_SZ + (size_t)D_ * FF_;

        // ln1 -> h (split)
        ln_kernel<<<M_, 256>>>(x, ln1g + (size_t)l * D_, ln1b + (size_t)l * D_, hh, hl);

        // fused q|k|v projection: N=3072, segmented output into q/k/v buffers
        gemm<0>(hh, hl, wqkvh, wqkvl, bqkv + (size_t)l * 3072, nullptr, qh, ql,
                M_, 3 * D_, D_, D_, D_, D_, (long long)MD_, 10);

        // fused causal attention: o = softmax(q k^T / 8) v  (split in/out)
        fa_kernel<<<dim3(T_ / 128, B_ * H_), 256, FA_SMEM>>>(qh, ql, kh, kl, vh, vl, oh, ol);

        // x = x + O @ Wo + bo  (fp32 residual)
        gemm<2>(oh, ol, woh, wol, bo + (size_t)l * D_, x, x, nullptr, M_, D_, D_, D_, D_, D_);

        // ln2 -> h (split)
        ln_kernel<<<M_, 256>>>(x, ln2g + (size_t)l * D_, ln2b + (size_t)l * D_, hh, hl);

        // ff = gelu(h @ W1 + b1) -> split
        gemm<1>(hh, hl, w1h, w1l, b1 + (size_t)l * FF_, nullptr, fh, fl, M_, FF_, D_, D_, D_, FF_);

        // x = x + ff @ W2 + b2
        gemm<2>(fh, fl, w2h, w2l, b2 + (size_t)l * D_, x, x, nullptr, M_, D_, FF_, FF_, FF_, D_);
    }

    // final LN + head (fp32 out)
    ln_kernel<<<M_, 256>>>(x, lnfg, lnfb, hh, hl);
    gemm<3>(hh, hl, whi + off_wh, wlo + off_wh, bh, nullptr, (float*)d_out, nullptr, M_, V_, D_, D_, D_, V_);
}